// round 6
// baseline (speedup 1.0000x reference)
#include <cuda_runtime.h>
#include <cstdint>
#include <math.h>

// Problem constants (dataset-fixed shapes)
#define LAMBDA   1e-3f
#define KDIM     128      // k
#define DDIM     256      // d
#define NSPLIT   74       // split-K chunks (74 * 2 tensors = 148 CTAs = 1 wave)
#define KB       16       // K per mainloop stage
#define NB       16       // Cholesky block size

// Scratch (device globals only)
__device__ float g_partial[2 * NSPLIT * KDIM * DDIM];   // 19.4 MB split-K partials
__device__ float g_A[KDIM * DDIM];
__device__ float g_B[KDIM * DDIM];
__device__ float g_AAt[KDIM * KDIM];
__device__ float g_BAt[KDIM * KDIM];

// ---------------------------------------------------------------------------
// helpers
// ---------------------------------------------------------------------------
__device__ __forceinline__ uint32_t smem_u32(const void* p) {
    uint32_t a;
    asm("{ .reg .u64 t; cvta.to.shared.u64 t, %1; cvt.u32.u64 %0, t; }" : "=r"(a) : "l"(p));
    return a;
}
__device__ __forceinline__ void sts64d(uint32_t a, float v) {   // duplicated pair
    asm volatile("st.shared.v2.f32 [%0], {%1,%1};" :: "r"(a), "f"(v) : "memory");
}
__device__ __forceinline__ void sts128(uint32_t a, float x, float y, float z, float w) {
    asm volatile("st.shared.v4.f32 [%0], {%1,%2,%3,%4};" :: "r"(a), "f"(x), "f"(y), "f"(z), "f"(w) : "memory");
}
// 16B shared load returning two 64-bit packed f32x2 operands
__device__ __forceinline__ void lds_2x64(uint32_t a, unsigned long long& x, unsigned long long& y) {
    asm volatile("ld.shared.v2.b64 {%0,%1}, [%2];" : "=l"(x), "=l"(y) : "r"(a));
}
// packed dual FMA: acc.f32x2 += a.f32x2 * b.f32x2
__device__ __forceinline__ void ffma2(unsigned long long& acc, unsigned long long a, unsigned long long b) {
    asm("fma.rn.f32x2 %0, %1, %2, %0;" : "+l"(acc) : "l"(a), "l"(b));
}

// ---------------------------------------------------------------------------
// SMEM layout per stage:
//   sA: KB rows x 1040B  (128 m as duplicated pairs: m at byte m*8, stride padded
//        to 1040 so different kk rows land on different bank groups)
//   sB: KB rows x 1024B  (256 n, 16B chunk c stored at phys c ^ ((c>>3)&3))
// ---------------------------------------------------------------------------
#define A_ROW      1040
#define A_BYTES    (KB * A_ROW)              // 16640
#define B_BYTES    (KB * 1024)               // 16384
#define STAGE      (A_BYTES + B_BYTES)       // 33024
#define SMEM_GEMM  (2 * STAGE)               // 66048

// ---------------------------------------------------------------------------
// Kernel 1: fp32 FFMA2 split-K GEMM.
//   partial[z,s][128, 256] = E[z][:, k0:k1] @ F[z][k0:k1, :]
// ---------------------------------------------------------------------------
__global__ __launch_bounds__(256, 1)
void gemm_f32x2(const float* __restrict__ Ex, const float* __restrict__ Fx,
                const float* __restrict__ Ey, const float* __restrict__ Fy,
                int N, int d, int Kc, int kd)
{
    extern __shared__ char smem[];
    const uint32_t sbase = smem_u32(smem);

    const int s = blockIdx.x;              // split-K chunk
    const int z = blockIdx.y;              // tensor select
    const float* __restrict__ E = z ? Ey : Ex;
    const float* __restrict__ F = z ? Fy : Fx;

    const int k0 = s * Kc;
    const int k1 = min(k0 + Kc, N);
    const int nstages = (k1 - k0 + KB - 1) / KB;

    const int tid = threadIdx.x;
    const int tx  = tid & 15;              // n  = tx*16 .. +15
    const int ty  = tid >> 4;              // m  = ty*8  .. +7

    // B chunk physical offsets for this thread (XOR swizzle hoisted)
    const uint32_t xv = (uint32_t)((tx >> 1) & 3);
    uint32_t bco[4];
    #pragma unroll
    for (int j = 0; j < 4; j++) bco[j] = (uint32_t)(((tx * 4 + j) ^ xv) << 4);
    const uint32_t aco = (uint32_t)(ty * 64);

    unsigned long long acc[8][8];
    #pragma unroll
    for (int i = 0; i < 8; i++)
        #pragma unroll
        for (int j = 0; j < 8; j++) acc[i][j] = 0ull;

    float4 ra[2], rb[4];

    // ---- prologue: load stage 0 ----
    {
        const int kt = k0;
        const bool full = (kt + KB) <= k1;
        #pragma unroll
        for (int r = 0; r < 2; r++) {
            int f = tid + r * 256;
            int m = f >> 2, kq = f & 3;
            if (full) {
                ra[r] = *(const float4*)(E + (size_t)m * N + kt + kq * 4);
            } else {
                float tv[4];
                #pragma unroll
                for (int jj = 0; jj < 4; jj++) {
                    int kk2 = kt + kq * 4 + jj;
                    tv[jj] = (kk2 < k1) ? E[(size_t)m * N + kk2] : 0.f;
                }
                ra[r] = make_float4(tv[0], tv[1], tv[2], tv[3]);
            }
        }
        #pragma unroll
        for (int r = 0; r < 4; r++) {
            int f = tid + r * 256;
            int krow = f >> 6, nq = f & 63;
            int kk2 = kt + krow;
            rb[r] = (kk2 < k1) ? *(const float4*)(F + (size_t)kk2 * d + nq * 4)
                               : make_float4(0.f, 0.f, 0.f, 0.f);
        }
    }

    for (int t = 0; t < nstages; t++) {
        const uint32_t sA = sbase + (t & 1) * STAGE;
        const uint32_t sB = sA + A_BYTES;

        // ---- STS stage t ----
        #pragma unroll
        for (int r = 0; r < 2; r++) {
            int f = tid + r * 256;
            int m = f >> 2, kq = f & 3;
            float v[4] = {ra[r].x, ra[r].y, ra[r].z, ra[r].w};
            #pragma unroll
            for (int jj = 0; jj < 4; jj++)
                sts64d(sA + (uint32_t)((kq * 4 + jj) * A_ROW + m * 8), v[jj]);
        }
        #pragma unroll
        for (int r = 0; r < 4; r++) {
            int f = tid + r * 256;
            int krow = f >> 6, nq = f & 63;
            uint32_t off = (uint32_t)(krow * 1024 + ((nq ^ ((nq >> 3) & 3)) << 4));
            sts128(sB + off, rb[r].x, rb[r].y, rb[r].z, rb[r].w);
        }
        __syncthreads();

        // ---- prefetch stage t+1 ----
        if (t + 1 < nstages) {
            const int kt = k0 + (t + 1) * KB;
            const bool full = (kt + KB) <= k1;
            #pragma unroll
            for (int r = 0; r < 2; r++) {
                int f = tid + r * 256;
                int m = f >> 2, kq = f & 3;
                if (full) {
                    ra[r] = *(const float4*)(E + (size_t)m * N + kt + kq * 4);
                } else {
                    float tv[4];
                    #pragma unroll
                    for (int jj = 0; jj < 4; jj++) {
                        int kk2 = kt + kq * 4 + jj;
                        tv[jj] = (kk2 < k1) ? E[(size_t)m * N + kk2] : 0.f;
                    }
                    ra[r] = make_float4(tv[0], tv[1], tv[2], tv[3]);
                }
            }
            #pragma unroll
            for (int r = 0; r < 4; r++) {
                int f = tid + r * 256;
                int krow = f >> 6, nq = f & 63;
                int kk2 = kt + krow;
                rb[r] = (kk2 < k1) ? *(const float4*)(F + (size_t)kk2 * d + nq * 4)
                                   : make_float4(0.f, 0.f, 0.f, 0.f);
            }
        }

        // ---- compute stage t: KB k-steps of 8x16 microtile in f32x2 ----
        #pragma unroll
        for (int kk = 0; kk < KB; kk++) {
            const uint32_t abase = sA + (uint32_t)(kk * A_ROW) + aco;
            const uint32_t bbase = sB + (uint32_t)(kk * 1024);
            unsigned long long a[8], b[8];
            lds_2x64(abase +  0, a[0], a[1]);
            lds_2x64(abase + 16, a[2], a[3]);
            lds_2x64(abase + 32, a[4], a[5]);
            lds_2x64(abase + 48, a[6], a[7]);
            lds_2x64(bbase + bco[0], b[0], b[1]);
            lds_2x64(bbase + bco[1], b[2], b[3]);
            lds_2x64(bbase + bco[2], b[4], b[5]);
            lds_2x64(bbase + bco[3], b[6], b[7]);
            #pragma unroll
            for (int i = 0; i < 8; i++)
                #pragma unroll
                for (int j = 0; j < 8; j++)
                    ffma2(acc[i][j], a[i], b[j]);
        }
        __syncthreads();
    }

    // ---- epilogue: write split-K partial tile ----
    float* P = g_partial + (size_t)(z * NSPLIT + s) * kd;
    #pragma unroll
    for (int i = 0; i < 8; i++) {
        int row = ty * 8 + i;
        float* dst = P + (size_t)row * DDIM + tx * 16;
        #pragma unroll
        for (int j = 0; j < 4; j++) {
            float2 p0 = *(float2*)&acc[i][2 * j];
            float2 p1 = *(float2*)&acc[i][2 * j + 1];
            *(float4*)(dst + j * 4) = make_float4(p0.x, p0.y, p1.x, p1.y);
        }
    }
}

// ---------------------------------------------------------------------------
// Kernel 2: deterministic split-K reduction -> g_A, g_B  ([k, d])
// ---------------------------------------------------------------------------
__global__ void reduce_partials(int kd)
{
    int idx = blockIdx.x * blockDim.x + threadIdx.x;
    if (idx >= 2 * kd) return;
    int z = idx / kd;
    int e = idx - z * kd;
    const float* P = g_partial + (size_t)z * NSPLIT * kd;
    float sum = 0.f;
    #pragma unroll 4
    for (int s = 0; s < NSPLIT; s++) sum += P[(size_t)s * kd + e];
    (z ? g_B : g_A)[e] = sum;
}

// ---------------------------------------------------------------------------
// Kernel 3: Gram matrices. AAt[i,j] = A_i . A_j ;  BAt[i,j] = B_i . A_j
// ---------------------------------------------------------------------------
__global__ __launch_bounds__(KDIM)
void gram_kernel(int k, int d)
{
    __shared__ float row[DDIM];
    const int i = blockIdx.x;
    const int z = blockIdx.y;
    const int j = threadIdx.x;
    const float* src = z ? g_B : g_A;
    for (int t = j; t < d; t += KDIM) row[t] = src[i * d + t];
    __syncthreads();
    const float* aj = g_A + j * d;
    float sum = 0.f;
    #pragma unroll 8
    for (int t = 0; t < d; t++) sum = fmaf(row[t], aj[t], sum);
    (z ? g_BAt : g_AAt)[i * k + j] = sum;
}

// ---------------------------------------------------------------------------
// Kernel 4: one CTA per output row i. Blocked Cholesky (NB=16) + fwd/bwd subs.
// ---------------------------------------------------------------------------
__global__ __launch_bounds__(512, 1)
void solve_kernel(const float* __restrict__ evx, const float* __restrict__ evy,
                  float* __restrict__ out)
{
    __shared__ float P[KDIM * (KDIM + 1) / 2];
    __shared__ float colb[NB][KDIM];
    __shared__ float yv[KDIM];
    __shared__ float invD[KDIM];

    const int i   = blockIdx.x;
    const int tid = threadIdx.x;
    const int t   = tid & 127;
    const int q   = tid >> 7;
    const int trit = t * (t + 1) / 2;

    for (int r0 = 0; r0 < KDIM; r0 += 4) {
        int r = r0 + q;
        if (t <= r) P[r * (r + 1) / 2 + t] = g_AAt[r * KDIM + t];
    }
    if (tid < KDIM) yv[tid] = g_BAt[i * KDIM + tid];
    __syncthreads();

    if (tid < KDIM) {
        float ev = evx[tid] - evy[i];
        P[trit + tid] += LAMBDA * ev * ev;
    }
    __syncthreads();

    for (int b = 0; b < KDIM / NB; b++) {
        const int j0  = b * NB;
        const int rlo = j0 + NB;

        if (tid < 32) {
            int lrow = tid & 15;
            int row = j0 + lrow;
            int trow = row * (row + 1) / 2;
            float dreg[NB];
            float myinv = 0.f;
            #pragma unroll
            for (int c = 0; c < NB; c++)
                dreg[c] = (c <= lrow) ? P[trow + j0 + c] : 0.f;

            #pragma unroll
            for (int c = 0; c < NB; c++) {
                float dc = __shfl_sync(0xffffffffu, dreg[c], c);
                float r  = rsqrtf(dc);
                if (lrow == c)      { dreg[c] = dc * r; myinv = r; }
                else if (lrow > c)  dreg[c] *= r;
                #pragma unroll
                for (int m = c + 1; m < NB; m++) {
                    float Lmc = __shfl_sync(0xffffffffu, dreg[c], m);
                    if (lrow >= m) dreg[m] -= dreg[c] * Lmc;
                }
            }
            if (tid < 16) {
                #pragma unroll
                for (int c = 0; c < NB; c++)
                    if (c <= lrow) P[trow + j0 + c] = dreg[c];
                invD[row] = myinv;
            }
        }
        __syncthreads();

        if (rlo >= KDIM) break;

        {
            int r = rlo + tid;
            if (r < KDIM) {
                int trr = r * (r + 1) / 2;
                float a[NB];
                #pragma unroll
                for (int j = 0; j < NB; j++) a[j] = P[trr + j0 + j];
                #pragma unroll
                for (int j = 0; j < NB; j++) {
                    float v = a[j];
                    int trj = (j0 + j) * (j0 + j + 1) / 2;
                    #pragma unroll
                    for (int c = 0; c < j; c++)
                        v -= a[c] * P[trj + j0 + c];
                    a[j] = v * invD[j0 + j];
                }
                #pragma unroll
                for (int j = 0; j < NB; j++) {
                    P[trr + j0 + j] = a[j];
                    colb[j][r] = a[j];
                }
            }
        }
        __syncthreads();

        if (t >= rlo) {
            float ar[NB];
            #pragma unroll
            for (int j = 0; j < NB; j++) ar[j] = colb[j][t];
            for (int c = rlo + q; c <= t; c += 4) {
                float a2 = P[trit + c];
                #pragma unroll
                for (int j = 0; j < NB; j++) a2 -= ar[j] * colb[j][c];
                P[trit + c] = a2;
            }
        }
        __syncthreads();
    }

    for (int b = 0; b < KDIM / NB; b++) {
        const int j0 = b * NB;
        if (tid < 32) {
            int lrow = tid & 15;
            int row = j0 + lrow;
            int trow = row * (row + 1) / 2;
            float yl = yv[row];
            #pragma unroll
            for (int c = 0; c < NB; c++) {
                int rc = j0 + c;
                float t2 = yl * invD[rc];
                yl = (lrow == c) ? t2 : yl;
                float yc = __shfl_sync(0xffffffffu, yl, c);
                if (lrow > c) yl -= P[trow + rc] * yc;
            }
            if (tid < 16) yv[row] = yl;
        }
        __syncthreads();
        {
            int r = j0 + NB + tid;
            if (r < KDIM) {
                int trr = r * (r + 1) / 2;
                float a2 = yv[r];
                #pragma unroll
                for (int c = 0; c < NB; c++)
                    a2 -= P[trr + j0 + c] * yv[j0 + c];
                yv[r] = a2;
            }
        }
        __syncthreads();
    }

    for (int b = KDIM / NB - 1; b >= 0; b--) {
        const int j0 = b * NB;
        if (tid < 32) {
            int lrow = tid & 15;
            int row = j0 + lrow;
            float xl = yv[row];
            #pragma unroll
            for (int c = NB - 1; c >= 0; c--) {
                int rc = j0 + c;
                int trc = rc * (rc + 1) / 2;
                float t2 = xl * invD[rc];
                xl = (lrow == c) ? t2 : xl;
                float xc = __shfl_sync(0xffffffffu, xl, c);
                if (lrow < c) xl -= P[trc + row] * xc;
            }
            if (tid < 16) yv[row] = xl;
        }
        __syncthreads();
        {
            int r = tid;
            if (r < j0) {
                float a2 = yv[r];
                #pragma unroll
                for (int c = 0; c < NB; c++) {
                    int rc = j0 + c;
                    a2 -= P[rc * (rc + 1) / 2 + r] * yv[rc];
                }
                yv[r] = a2;
            }
        }
        __syncthreads();
    }

    if (tid < KDIM) out[i * KDIM + tid] = yv[tid];
}

// ---------------------------------------------------------------------------
// Launch
// ---------------------------------------------------------------------------
extern "C" void kernel_launch(void* const* d_in, const int* in_sizes, int n_in,
                              void* d_out, int out_size)
{
    const float* feat_x = (const float*)d_in[0];
    const float* feat_y = (const float*)d_in[1];
    const float* evals_x = (const float*)d_in[2];
    const float* evals_y = (const float*)d_in[3];
    const float* Ex = (const float*)d_in[4];
    const float* Ey = (const float*)d_in[5];

    const int  k  = in_sizes[2];                  // 128
    const long N  = (long)in_sizes[4] / k;        // 200000
    const int  d  = (int)((long)in_sizes[0] / N); // 256
    const int  kd = k * d;

    int Kc = (int)((N + NSPLIT - 1) / NSPLIT);
    Kc = ((Kc + KB - 1) / KB) * KB;

    cudaFuncSetAttribute(gemm_f32x2, cudaFuncAttributeMaxDynamicSharedMemorySize, SMEM_GEMM);

    dim3 ggrid(NSPLIT, 2);
    gemm_f32x2<<<ggrid, 256, SMEM_GEMM>>>(Ex, feat_x, Ey, feat_y, (int)N, d, Kc, kd);

    reduce_partials<<<(2 * kd + 255) / 256, 256>>>(kd);

    gram_kernel<<<dim3(k, 2), KDIM>>>(k, d);

    solve_kernel<<<k, 512>>>(evals_x, evals_y, (float*)d_out);
}

// round 7
// speedup vs baseline: 1.8598x; 1.8598x over previous
#include <cuda_runtime.h>
#include <cstdint>
#include <math.h>

// Problem constants (dataset-fixed shapes)
#define LAMBDA   1e-3f
#define KDIM     128      // k
#define DDIM     256      // d
#define NSPLIT   37       // split-K chunks (2 ntiles * 37 * 2 tensors = 148 CTAs = 1 wave)
#define KB       32       // K per mainloop stage
#define NB       16       // Cholesky block size

// Scratch (device globals only)
__device__ float g_partial[2 * NSPLIT * KDIM * DDIM];   // ~9.7 MB split-K partials
__device__ float g_A[KDIM * DDIM];
__device__ float g_B[KDIM * DDIM];
__device__ float g_AAt[KDIM * KDIM];
__device__ float g_BAt[KDIM * KDIM];

// ---------------------------------------------------------------------------
// helpers
// ---------------------------------------------------------------------------
__device__ __forceinline__ uint32_t smem_u32(const void* p) {
    uint32_t a;
    asm("{ .reg .u64 t; cvta.to.shared.u64 t, %1; cvt.u32.u64 %0, t; }" : "=r"(a) : "l"(p));
    return a;
}
__device__ __forceinline__ float f2tf32(float x) {
    uint32_t r;
    asm("cvt.rna.tf32.f32 %0, %1;" : "=r"(r) : "f"(x));
    return __uint_as_float(r);
}
__device__ __forceinline__ void sts128(uint32_t a, float x, float y, float z, float w) {
    asm volatile("st.shared.v4.f32 [%0], {%1,%2,%3,%4};" :: "r"(a), "f"(x), "f"(y), "f"(z), "f"(w) : "memory");
}
__device__ __forceinline__ uint32_t lds32(uint32_t a) {
    uint32_t v;
    asm volatile("ld.shared.b32 %0, [%1];" : "=r"(v) : "r"(a));
    return v;
}
__device__ __forceinline__ void ldsm_x4(uint32_t addr, uint32_t& r0, uint32_t& r1, uint32_t& r2, uint32_t& r3) {
    asm volatile("ldmatrix.sync.aligned.m8n8.x4.shared.b16 {%0,%1,%2,%3}, [%4];"
                 : "=r"(r0), "=r"(r1), "=r"(r2), "=r"(r3) : "r"(addr));
}
// tf32 mma: D(16x8) += A(16x8) * B(8x8)
__device__ __forceinline__ void mma_tf32(float* c,
                                         uint32_t a0, uint32_t a1, uint32_t a2, uint32_t a3,
                                         uint32_t b0, uint32_t b1) {
    asm volatile(
        "mma.sync.aligned.m16n8k8.row.col.f32.tf32.tf32.f32 "
        "{%0,%1,%2,%3}, {%4,%5,%6,%7}, {%8,%9}, {%0,%1,%2,%3};"
        : "+f"(c[0]), "+f"(c[1]), "+f"(c[2]), "+f"(c[3])
        : "r"(a0), "r"(a1), "r"(a2), "r"(a3), "r"(b0), "r"(b1));
}

// ---------------------------------------------------------------------------
// SMEM layout per stage (all strides chosen conflict-free, verified on paper):
//   A planes (hi,lo): 128 m-rows x 36 floats (144B row stride; 32 k used)
//   B planes (hi,lo):  32 k-rows x 136 floats (544B row stride; 128 n used)
// ---------------------------------------------------------------------------
#define A_ROWB   144
#define AP       (128 * A_ROWB)              // 18432 bytes per A plane
#define B_ROWB   544
#define BP       (32 * B_ROWB)               // 17408 bytes per B plane
#define STAGE    (2 * AP + 2 * BP)           // 71680
#define SMEM_GEMM (2 * STAGE)                // 143360

// ---------------------------------------------------------------------------
// Kernel 1: 3xTF32 mma.sync split-K GEMM (conflict-free smem, ldmatrix A).
//   partial[z,s][128, ntile*128 .. +128] = E[z][:, k0:k1] @ F[z][k0:k1, tile]
// ---------------------------------------------------------------------------
__global__ __launch_bounds__(256, 1)
void gemm_mma(const float* __restrict__ Ex, const float* __restrict__ Fx,
              const float* __restrict__ Ey, const float* __restrict__ Fy,
              int N, int d, int Kc, int kd)
{
    extern __shared__ char smem[];
    const uint32_t sbase = smem_u32(smem);

    const int ntile = blockIdx.x;          // 0,1 -> which 128 of d=256
    const int s     = blockIdx.y;          // split-K chunk
    const int z     = blockIdx.z;          // tensor select
    const float* __restrict__ E = z ? Ey : Ex;
    const float* __restrict__ F = z ? Fy : Fx;

    const int k0 = s * Kc;
    const int k1 = min(k0 + Kc, N);
    const int nstages = (k1 - k0 + KB - 1) / KB;

    const int tid  = threadIdx.x;
    const int l    = tid & 31;
    const int wid  = tid >> 5;
    const int warpM = wid & 3;             // 4 warps over M -> 32 rows each
    const int warpN = wid >> 2;            // 2 warps over N -> 64 cols each
    const int mbase = warpM * 32;

    // per-lane hoisted fragment address pieces
    const uint32_t a_lane = (uint32_t)(((((l >> 3) & 1) * 8 + (l & 7)) * A_ROWB) + ((l >> 4) << 4))
                          + (uint32_t)(mbase * A_ROWB);
    const uint32_t b_lane = (uint32_t)((l & 3) * B_ROWB + (warpN * 64 + (l >> 2)) * 4);

    float acc[2][8][4];
    #pragma unroll
    for (int a = 0; a < 2; a++)
        #pragma unroll
        for (int b = 0; b < 8; b++)
            #pragma unroll
            for (int c = 0; c < 4; c++) acc[a][b][c] = 0.f;

    float4 ra[4], rb[4];

    // ---- prologue: load stage 0 into registers ----
    {
        const int kt = k0;
        const bool full = (kt + KB) <= k1;
        #pragma unroll
        for (int r = 0; r < 4; r++) {
            int f = tid + r * 256;
            int m = f >> 3, q = f & 7;
            if (full) {
                ra[r] = *(const float4*)(E + (size_t)m * N + kt + q * 4);
            } else {
                float tv[4];
                #pragma unroll
                for (int jj = 0; jj < 4; jj++) {
                    int kk2 = kt + q * 4 + jj;
                    tv[jj] = (kk2 < k1) ? E[(size_t)m * N + kk2] : 0.f;
                }
                ra[r] = make_float4(tv[0], tv[1], tv[2], tv[3]);
            }
        }
        #pragma unroll
        for (int r = 0; r < 4; r++) {
            int f = tid + r * 256;
            int krow = f >> 5, nq = f & 31;
            int kk2 = kt + krow;
            rb[r] = (kk2 < k1) ? *(const float4*)(F + (size_t)kk2 * d + ntile * 128 + nq * 4)
                               : make_float4(0.f, 0.f, 0.f, 0.f);
        }
    }

    for (int t = 0; t < nstages; t++) {
        const uint32_t sAh = sbase + (t & 1) * STAGE;
        const uint32_t sAl = sAh + AP;
        const uint32_t sBh = sAl + AP;
        const uint32_t sBl = sBh + BP;

        // ---- STS stage t (hi/lo split) ----
        #pragma unroll
        for (int r = 0; r < 4; r++) {
            int f = tid + r * 256;
            int m = f >> 3, q = f & 7;
            float v[4] = {ra[r].x, ra[r].y, ra[r].z, ra[r].w};
            float h[4], lo[4];
            #pragma unroll
            for (int jj = 0; jj < 4; jj++) { h[jj] = f2tf32(v[jj]); lo[jj] = f2tf32(v[jj] - h[jj]); }
            uint32_t off = (uint32_t)(m * A_ROWB + q * 16);
            sts128(sAh + off, h[0], h[1], h[2], h[3]);
            sts128(sAl + off, lo[0], lo[1], lo[2], lo[3]);
        }
        #pragma unroll
        for (int r = 0; r < 4; r++) {
            int f = tid + r * 256;
            int krow = f >> 5, nq = f & 31;
            float v[4] = {rb[r].x, rb[r].y, rb[r].z, rb[r].w};
            float h[4], lo[4];
            #pragma unroll
            for (int jj = 0; jj < 4; jj++) { h[jj] = f2tf32(v[jj]); lo[jj] = f2tf32(v[jj] - h[jj]); }
            uint32_t off = (uint32_t)(krow * B_ROWB + nq * 16);
            sts128(sBh + off, h[0], h[1], h[2], h[3]);
            sts128(sBl + off, lo[0], lo[1], lo[2], lo[3]);
        }
        __syncthreads();

        // ---- prefetch stage t+1 into registers ----
        if (t + 1 < nstages) {
            const int kt = k0 + (t + 1) * KB;
            const bool full = (kt + KB) <= k1;
            #pragma unroll
            for (int r = 0; r < 4; r++) {
                int f = tid + r * 256;
                int m = f >> 3, q = f & 7;
                if (full) {
                    ra[r] = *(const float4*)(E + (size_t)m * N + kt + q * 4);
                } else {
                    float tv[4];
                    #pragma unroll
                    for (int jj = 0; jj < 4; jj++) {
                        int kk2 = kt + q * 4 + jj;
                        tv[jj] = (kk2 < k1) ? E[(size_t)m * N + kk2] : 0.f;
                    }
                    ra[r] = make_float4(tv[0], tv[1], tv[2], tv[3]);
                }
            }
            #pragma unroll
            for (int r = 0; r < 4; r++) {
                int f = tid + r * 256;
                int krow = f >> 5, nq = f & 31;
                int kk2 = kt + krow;
                rb[r] = (kk2 < k1) ? *(const float4*)(F + (size_t)kk2 * d + ntile * 128 + nq * 4)
                                   : make_float4(0.f, 0.f, 0.f, 0.f);
            }
        }

        // ---- compute stage t: 4 k-chunks of 8 ----
        #pragma unroll
        for (int kc = 0; kc < 4; kc++) {
            // A fragments: 1 ldmatrix.x4 per (mt, plane)
            uint32_t ah[2][4], al[2][4];
            #pragma unroll
            for (int mt = 0; mt < 2; mt++) {
                uint32_t aoff = a_lane + (uint32_t)(mt * 16 * A_ROWB) + (uint32_t)(kc * 32);
                ldsm_x4(sAh + aoff, ah[mt][0], ah[mt][1], ah[mt][2], ah[mt][3]);
                ldsm_x4(sAl + aoff, al[mt][0], al[mt][1], al[mt][2], al[mt][3]);
            }
            const uint32_t b0off = b_lane + (uint32_t)(kc * 8 * B_ROWB);
            #pragma unroll
            for (int j = 0; j < 8; j++) {
                uint32_t boff = b0off + (uint32_t)(j * 32);
                uint32_t b0h = lds32(sBh + boff);
                uint32_t b1h = lds32(sBh + boff + 4 * B_ROWB);
                uint32_t b0l = lds32(sBl + boff);
                uint32_t b1l = lds32(sBl + boff + 4 * B_ROWB);
                mma_tf32(acc[0][j], ah[0][0], ah[0][1], ah[0][2], ah[0][3], b0h, b1h);  // hh
                mma_tf32(acc[0][j], al[0][0], al[0][1], al[0][2], al[0][3], b0h, b1h);  // lh
                mma_tf32(acc[0][j], ah[0][0], ah[0][1], ah[0][2], ah[0][3], b0l, b1l);  // hl
                mma_tf32(acc[1][j], ah[1][0], ah[1][1], ah[1][2], ah[1][3], b0h, b1h);
                mma_tf32(acc[1][j], al[1][0], al[1][1], al[1][2], al[1][3], b0h, b1h);
                mma_tf32(acc[1][j], ah[1][0], ah[1][1], ah[1][2], ah[1][3], b0l, b1l);
            }
        }
        __syncthreads();
    }

    // ---- epilogue: write split-K partial tile ----
    float* P = g_partial + (size_t)(z * NSPLIT + s) * kd;
    const int rsub = l >> 2;
    const int csub = (l & 3) * 2;
    #pragma unroll
    for (int mt = 0; mt < 2; mt++) {
        #pragma unroll
        for (int j = 0; j < 8; j++) {
            int row = mbase + mt * 16 + rsub;
            int col = ntile * 128 + warpN * 64 + j * 8 + csub;
            *(float2*)(P + (size_t)row * DDIM + col)       = make_float2(acc[mt][j][0], acc[mt][j][1]);
            *(float2*)(P + (size_t)(row + 8) * DDIM + col) = make_float2(acc[mt][j][2], acc[mt][j][3]);
        }
    }
}

// ---------------------------------------------------------------------------
// Kernel 2: deterministic split-K reduction -> g_A, g_B  ([k, d])
// ---------------------------------------------------------------------------
__global__ void reduce_partials(int kd)
{
    int idx = blockIdx.x * blockDim.x + threadIdx.x;
    if (idx >= 2 * kd) return;
    int z = idx / kd;
    int e = idx - z * kd;
    const float* P = g_partial + (size_t)z * NSPLIT * kd;
    float sum = 0.f;
    #pragma unroll 4
    for (int s = 0; s < NSPLIT; s++) sum += P[(size_t)s * kd + e];
    (z ? g_B : g_A)[e] = sum;
}

// ---------------------------------------------------------------------------
// Kernel 3: Gram matrices. AAt[i,j] = A_i . A_j ;  BAt[i,j] = B_i . A_j
// ---------------------------------------------------------------------------
__global__ __launch_bounds__(KDIM)
void gram_kernel(int k, int d)
{
    __shared__ float row[DDIM];
    const int i = blockIdx.x;
    const int z = blockIdx.y;
    const int j = threadIdx.x;
    const float* src = z ? g_B : g_A;
    for (int t = j; t < d; t += KDIM) row[t] = src[i * d + t];
    __syncthreads();
    const float* aj = g_A + j * d;
    float sum = 0.f;
    #pragma unroll 8
    for (int t = 0; t < d; t++) sum = fmaf(row[t], aj[t], sum);
    (z ? g_BAt : g_AAt)[i * k + j] = sum;
}

// ---------------------------------------------------------------------------
// Kernel 4: one CTA per output row i. Blocked Cholesky (NB=16) + fwd/bwd subs.
// ---------------------------------------------------------------------------
__global__ __launch_bounds__(512, 1)
void solve_kernel(const float* __restrict__ evx, const float* __restrict__ evy,
                  float* __restrict__ out)
{
    __shared__ float P[KDIM * (KDIM + 1) / 2];
    __shared__ float colb[NB][KDIM];
    __shared__ float yv[KDIM];
    __shared__ float invD[KDIM];

    const int i   = blockIdx.x;
    const int tid = threadIdx.x;
    const int t   = tid & 127;
    const int q   = tid >> 7;
    const int trit = t * (t + 1) / 2;

    for (int r0 = 0; r0 < KDIM; r0 += 4) {
        int r = r0 + q;
        if (t <= r) P[r * (r + 1) / 2 + t] = g_AAt[r * KDIM + t];
    }
    if (tid < KDIM) yv[tid] = g_BAt[i * KDIM + tid];
    __syncthreads();

    if (tid < KDIM) {
        float ev = evx[tid] - evy[i];
        P[trit + tid] += LAMBDA * ev * ev;
    }
    __syncthreads();

    for (int b = 0; b < KDIM / NB; b++) {
        const int j0  = b * NB;
        const int rlo = j0 + NB;

        if (tid < 32) {
            int lrow = tid & 15;
            int row = j0 + lrow;
            int trow = row * (row + 1) / 2;
            float dreg[NB];
            float myinv = 0.f;
            #pragma unroll
            for (int c = 0; c < NB; c++)
                dreg[c] = (c <= lrow) ? P[trow + j0 + c] : 0.f;

            #pragma unroll
            for (int c = 0; c < NB; c++) {
                float dc = __shfl_sync(0xffffffffu, dreg[c], c);
                float r  = rsqrtf(dc);
                if (lrow == c)      { dreg[c] = dc * r; myinv = r; }
                else if (lrow > c)  dreg[c] *= r;
                #pragma unroll
                for (int m = c + 1; m < NB; m++) {
                    float Lmc = __shfl_sync(0xffffffffu, dreg[c], m);
                    if (lrow >= m) dreg[m] -= dreg[c] * Lmc;
                }
            }
            if (tid < 16) {
                #pragma unroll
                for (int c = 0; c < NB; c++)
                    if (c <= lrow) P[trow + j0 + c] = dreg[c];
                invD[row] = myinv;
            }
        }
        __syncthreads();

        if (rlo >= KDIM) break;

        {
            int r = rlo + tid;
            if (r < KDIM) {
                int trr = r * (r + 1) / 2;
                float a[NB];
                #pragma unroll
                for (int j = 0; j < NB; j++) a[j] = P[trr + j0 + j];
                #pragma unroll
                for (int j = 0; j < NB; j++) {
                    float v = a[j];
                    int trj = (j0 + j) * (j0 + j + 1) / 2;
                    #pragma unroll
                    for (int c = 0; c < j; c++)
                        v -= a[c] * P[trj + j0 + c];
                    a[j] = v * invD[j0 + j];
                }
                #pragma unroll
                for (int j = 0; j < NB; j++) {
                    P[trr + j0 + j] = a[j];
                    colb[j][r] = a[j];
                }
            }
        }
        __syncthreads();

        if (t >= rlo) {
            float ar[NB];
            #pragma unroll
            for (int j = 0; j < NB; j++) ar[j] = colb[j][t];
            for (int c = rlo + q; c <= t; c += 4) {
                float a2 = P[trit + c];
                #pragma unroll
                for (int j = 0; j < NB; j++) a2 -= ar[j] * colb[j][c];
                P[trit + c] = a2;
            }
        }
        __syncthreads();
    }

    for (int b = 0; b < KDIM / NB; b++) {
        const int j0 = b * NB;
        if (tid < 32) {
            int lrow = tid & 15;
            int row = j0 + lrow;
            int trow = row * (row + 1) / 2;
            float yl = yv[row];
            #pragma unroll
            for (int c = 0; c < NB; c++) {
                int rc = j0 + c;
                float t2 = yl * invD[rc];
                yl = (lrow == c) ? t2 : yl;
                float yc = __shfl_sync(0xffffffffu, yl, c);
                if (lrow > c) yl -= P[trow + rc] * yc;
            }
            if (tid < 16) yv[row] = yl;
        }
        __syncthreads();
        {
            int r = j0 + NB + tid;
            if (r < KDIM) {
                int trr = r * (r + 1) / 2;
                float a2 = yv[r];
                #pragma unroll
                for (int c = 0; c < NB; c++)
                    a2 -= P[trr + j0 + c] * yv[j0 + c];
                yv[r] = a2;
            }
        }
        __syncthreads();
    }

    for (int b = KDIM / NB - 1; b >= 0; b--) {
        const int j0 = b * NB;
        if (tid < 32) {
            int lrow = tid & 15;
            int row = j0 + lrow;
            float xl = yv[row];
            #pragma unroll
            for (int c = NB - 1; c >= 0; c--) {
                int rc = j0 + c;
                int trc = rc * (rc + 1) / 2;
                float t2 = xl * invD[rc];
                xl = (lrow == c) ? t2 : xl;
                float xc = __shfl_sync(0xffffffffu, xl, c);
                if (lrow < c) xl -= P[trc + row] * xc;
            }
            if (tid < 16) yv[row] = xl;
        }
        __syncthreads();
        {
            int r = tid;
            if (r < j0) {
                float a2 = yv[r];
                #pragma unroll
                for (int c = 0; c < NB; c++) {
                    int rc = j0 + c;
                    a2 -= P[rc * (rc + 1) / 2 + r] * yv[rc];
                }
                yv[r] = a2;
            }
        }
        __syncthreads();
    }

    if (tid < KDIM) out[i * KDIM + tid] = yv[tid];
}

// ---------------------------------------------------------------------------
// Launch
// ---------------------------------------------------------------------------
extern "C" void kernel_launch(void* const* d_in, const int* in_sizes, int n_in,
                              void* d_out, int out_size)
{
    const float* feat_x = (const float*)d_in[0];
    const float* feat_y = (const float*)d_in[1];
    const float* evals_x = (const float*)d_in[2];
    const float* evals_y = (const float*)d_in[3];
    const float* Ex = (const float*)d_in[4];
    const float* Ey = (const float*)d_in[5];

    const int  k  = in_sizes[2];                  // 128
    const long N  = (long)in_sizes[4] / k;        // 200000
    const int  d  = (int)((long)in_sizes[0] / N); // 256
    const int  kd = k * d;

    int Kc = (int)((N + NSPLIT - 1) / NSPLIT);
    Kc = ((Kc + KB - 1) / KB) * KB;

    cudaFuncSetAttribute(gemm_mma, cudaFuncAttributeMaxDynamicSharedMemorySize, SMEM_GEMM);

    dim3 ggrid(2, NSPLIT, 2);
    gemm_mma<<<ggrid, 256, SMEM_GEMM>>>(Ex, feat_x, Ey, feat_y, (int)N, d, Kc, kd);

    reduce_partials<<<(2 * kd + 255) / 256, 256>>>(kd);

    gram_kernel<<<dim3(k, 2), KDIM>>>(k, d);

    solve_kernel<<<k, 512>>>(evals_x, evals_y, (float*)d_out);
}

// round 8
// speedup vs baseline: 2.9083x; 1.5638x over previous
#include <cuda_runtime.h>
#include <cuda_fp16.h>
#include <cstdint>
#include <math.h>

// Problem constants (dataset-fixed shapes)
#define LAMBDA   1e-3f
#define KDIM     128      // k
#define DDIM     256      // d
#define NSPLIT   37       // split-K chunks (2 ntiles * 37 * 2 tensors = 148 CTAs = 1 wave)
#define KB       32       // K per mainloop stage (2 x k16 chunks)
#define NB       16       // Cholesky block size
#define ESCALE   512.0f   // power-of-2 scale so E's lo-halves stay in fp16 normal range
#define EINV     (1.0f / 512.0f)

// Scratch (device globals only)
__device__ float g_partial[2 * NSPLIT * KDIM * DDIM];   // ~9.7 MB split-K partials
__device__ float g_A[KDIM * DDIM];
__device__ float g_B[KDIM * DDIM];
__device__ float g_AAt[KDIM * KDIM];
__device__ float g_BAt[KDIM * KDIM];

// ---------------------------------------------------------------------------
// helpers
// ---------------------------------------------------------------------------
__device__ __forceinline__ uint32_t smem_u32(const void* p) {
    uint32_t a;
    asm("{ .reg .u64 t; cvta.to.shared.u64 t, %1; cvt.u32.u64 %0, t; }" : "=r"(a) : "l"(p));
    return a;
}
__device__ __forceinline__ void sts64(uint32_t a, uint32_t x, uint32_t y) {
    asm volatile("st.shared.v2.b32 [%0], {%1,%2};" :: "r"(a), "r"(x), "r"(y) : "memory");
}
__device__ __forceinline__ void ldsm_x4(uint32_t addr, uint32_t& r0, uint32_t& r1, uint32_t& r2, uint32_t& r3) {
    asm volatile("ldmatrix.sync.aligned.m8n8.x4.shared.b16 {%0,%1,%2,%3}, [%4];"
                 : "=r"(r0), "=r"(r1), "=r"(r2), "=r"(r3) : "r"(addr));
}
__device__ __forceinline__ void ldsm_x4t(uint32_t addr, uint32_t& r0, uint32_t& r1, uint32_t& r2, uint32_t& r3) {
    asm volatile("ldmatrix.sync.aligned.m8n8.x4.trans.shared.b16 {%0,%1,%2,%3}, [%4];"
                 : "=r"(r0), "=r"(r1), "=r"(r2), "=r"(r3) : "r"(addr));
}
// fp16 mma: D(16x8) += A(16x16) * B(16x8), fp32 accum
__device__ __forceinline__ void mma_f16(float* c,
                                        uint32_t a0, uint32_t a1, uint32_t a2, uint32_t a3,
                                        uint32_t b0, uint32_t b1) {
    asm volatile(
        "mma.sync.aligned.m16n8k16.row.col.f32.f16.f16.f32 "
        "{%0,%1,%2,%3}, {%4,%5,%6,%7}, {%8,%9}, {%0,%1,%2,%3};"
        : "+f"(c[0]), "+f"(c[1]), "+f"(c[2]), "+f"(c[3])
        : "r"(a0), "r"(a1), "r"(a2), "r"(a3), "r"(b0), "r"(b1));
}
// split x (4 floats) into hi/lo half2 pairs (packed uint32)
__device__ __forceinline__ void split4(const float* v, uint32_t* hi, uint32_t* lo) {
    __half2 h0 = __floats2half2_rn(v[0], v[1]);
    __half2 h1 = __floats2half2_rn(v[2], v[3]);
    float2 f0 = __half22float2(h0);
    float2 f1 = __half22float2(h1);
    __half2 l0 = __floats2half2_rn(v[0] - f0.x, v[1] - f0.y);
    __half2 l1 = __floats2half2_rn(v[2] - f1.x, v[3] - f1.y);
    hi[0] = *(uint32_t*)&h0; hi[1] = *(uint32_t*)&h1;
    lo[0] = *(uint32_t*)&l0; lo[1] = *(uint32_t*)&l1;
}

// ---------------------------------------------------------------------------
// SMEM layout per stage (verified conflict-free bank rotations):
//   A planes (hi,lo): 128 m-rows x 80B (32 k halves = 64B + 16B pad)
//   B planes (hi,lo):  32 k-rows x 272B (128 n halves = 256B + 16B pad)
// ---------------------------------------------------------------------------
#define A_ROWB   80
#define AP       (128 * A_ROWB)              // 10240 per plane
#define B_ROWB   272
#define BP       (32 * B_ROWB)               // 8704 per plane
#define STAGE    (2 * AP + 2 * BP)           // 37888
#define SMEM_GEMM (2 * STAGE)                // 75776

// ---------------------------------------------------------------------------
// Kernel 1: 3xFP16 (Markidis split) mma.sync split-K GEMM.
//   partial[z,s][128, ntile*128 .. +128] = E[z][:, k0:k1] @ F[z][k0:k1, tile]
// ---------------------------------------------------------------------------
__global__ __launch_bounds__(256, 1)
void gemm_mma(const float* __restrict__ Ex, const float* __restrict__ Fx,
              const float* __restrict__ Ey, const float* __restrict__ Fy,
              int N, int d, int Kc, int kd)
{
    extern __shared__ char smem[];
    const uint32_t sbase = smem_u32(smem);

    const int ntile = blockIdx.x;          // 0,1 -> which 128 of d=256
    const int s     = blockIdx.y;          // split-K chunk
    const int z     = blockIdx.z;          // tensor select
    const float* __restrict__ E = z ? Ey : Ex;
    const float* __restrict__ F = z ? Fy : Fx;

    const int k0 = s * Kc;
    const int k1 = min(k0 + Kc, N);
    const int nstages = (k1 - k0 + KB - 1) / KB;

    const int tid  = threadIdx.x;
    const int l    = tid & 31;
    const int wid  = tid >> 5;
    const int warpM = wid & 3;             // 4 warps over M -> 32 rows each
    const int warpN = wid >> 2;            // 2 warps over N -> 64 cols each
    const int mbase = warpM * 32;

    // ldmatrix lane address pieces (same (l&15)*stride + (l>>4)*16 form for A and B)
    const uint32_t a_lane = (uint32_t)((l & 15) * A_ROWB + ((l >> 4) << 4)) + (uint32_t)(mbase * A_ROWB);
    const uint32_t b_lane = (uint32_t)((l & 15) * B_ROWB + ((l >> 4) << 4)) + (uint32_t)(warpN * 64 * 2);

    float acc[2][8][4];
    #pragma unroll
    for (int a = 0; a < 2; a++)
        #pragma unroll
        for (int b = 0; b < 8; b++)
            #pragma unroll
            for (int c = 0; c < 4; c++) acc[a][b][c] = 0.f;

    float4 ra[4], rb[4];

    // ---- prologue: load stage 0 into registers ----
    {
        const int kt = k0;
        const bool full = (kt + KB) <= k1;
        #pragma unroll
        for (int r = 0; r < 4; r++) {
            int f = tid + r * 256;
            int m = f >> 3, q = f & 7;
            if (full) {
                ra[r] = *(const float4*)(E + (size_t)m * N + kt + q * 4);
            } else {
                float tv[4];
                #pragma unroll
                for (int jj = 0; jj < 4; jj++) {
                    int kk2 = kt + q * 4 + jj;
                    tv[jj] = (kk2 < k1) ? E[(size_t)m * N + kk2] : 0.f;
                }
                ra[r] = make_float4(tv[0], tv[1], tv[2], tv[3]);
            }
        }
        #pragma unroll
        for (int r = 0; r < 4; r++) {
            int f = tid + r * 256;
            int krow = f >> 5, nq = f & 31;
            int kk2 = kt + krow;
            rb[r] = (kk2 < k1) ? *(const float4*)(F + (size_t)kk2 * d + ntile * 128 + nq * 4)
                               : make_float4(0.f, 0.f, 0.f, 0.f);
        }
    }

    for (int t = 0; t < nstages; t++) {
        const uint32_t sAh = sbase + (t & 1) * STAGE;
        const uint32_t sAl = sAh + AP;
        const uint32_t sBh = sAl + AP;
        const uint32_t sBl = sBh + BP;

        // ---- STS stage t (scale E, hi/lo split) ----
        #pragma unroll
        for (int r = 0; r < 4; r++) {
            int f = tid + r * 256;
            int m = f >> 3, q = f & 7;
            float v[4] = {ra[r].x * ESCALE, ra[r].y * ESCALE, ra[r].z * ESCALE, ra[r].w * ESCALE};
            uint32_t hi[2], lo[2];
            split4(v, hi, lo);
            uint32_t off = (uint32_t)(m * A_ROWB + q * 8);
            sts64(sAh + off, hi[0], hi[1]);
            sts64(sAl + off, lo[0], lo[1]);
        }
        #pragma unroll
        for (int r = 0; r < 4; r++) {
            int f = tid + r * 256;
            int krow = f >> 5, nq = f & 31;
            float v[4] = {rb[r].x, rb[r].y, rb[r].z, rb[r].w};
            uint32_t hi[2], lo[2];
            split4(v, hi, lo);
            uint32_t off = (uint32_t)(krow * B_ROWB + nq * 8);
            sts64(sBh + off, hi[0], hi[1]);
            sts64(sBl + off, lo[0], lo[1]);
        }
        __syncthreads();

        // ---- prefetch stage t+1 into registers ----
        if (t + 1 < nstages) {
            const int kt = k0 + (t + 1) * KB;
            const bool full = (kt + KB) <= k1;
            #pragma unroll
            for (int r = 0; r < 4; r++) {
                int f = tid + r * 256;
                int m = f >> 3, q = f & 7;
                if (full) {
                    ra[r] = *(const float4*)(E + (size_t)m * N + kt + q * 4);
                } else {
                    float tv[4];
                    #pragma unroll
                    for (int jj = 0; jj < 4; jj++) {
                        int kk2 = kt + q * 4 + jj;
                        tv[jj] = (kk2 < k1) ? E[(size_t)m * N + kk2] : 0.f;
                    }
                    ra[r] = make_float4(tv[0], tv[1], tv[2], tv[3]);
                }
            }
            #pragma unroll
            for (int r = 0; r < 4; r++) {
                int f = tid + r * 256;
                int krow = f >> 5, nq = f & 31;
                int kk2 = kt + krow;
                rb[r] = (kk2 < k1) ? *(const float4*)(F + (size_t)kk2 * d + ntile * 128 + nq * 4)
                                   : make_float4(0.f, 0.f, 0.f, 0.f);
            }
        }

        // ---- compute stage t: 2 k16 chunks ----
        #pragma unroll
        for (int kc = 0; kc < 2; kc++) {
            uint32_t ah[2][4], al[2][4];
            #pragma unroll
            for (int mt = 0; mt < 2; mt++) {
                uint32_t aoff = a_lane + (uint32_t)(mt * 16 * A_ROWB) + (uint32_t)(kc * 32);
                ldsm_x4(sAh + aoff, ah[mt][0], ah[mt][1], ah[mt][2], ah[mt][3]);
                ldsm_x4(sAl + aoff, al[mt][0], al[mt][1], al[mt][2], al[mt][3]);
            }
            const uint32_t bk = b_lane + (uint32_t)(kc * 16 * B_ROWB);
            #pragma unroll
            for (int jp = 0; jp < 4; jp++) {
                uint32_t bh[4], bl[4];
                uint32_t boff = bk + (uint32_t)(jp * 32);       // 16 n halves per pair
                ldsm_x4t(sBh + boff, bh[0], bh[1], bh[2], bh[3]);
                ldsm_x4t(sBl + boff, bl[0], bl[1], bl[2], bl[3]);
                #pragma unroll
                for (int je = 0; je < 2; je++) {               // j = 2*jp + je
                    const int j = 2 * jp + je;
                    uint32_t b0h = bh[2 * je], b1h = bh[2 * je + 1];
                    uint32_t b0l = bl[2 * je], b1l = bl[2 * je + 1];
                    mma_f16(acc[0][j], ah[0][0], ah[0][1], ah[0][2], ah[0][3], b0h, b1h);  // hh
                    mma_f16(acc[0][j], al[0][0], al[0][1], al[0][2], al[0][3], b0h, b1h);  // lh
                    mma_f16(acc[0][j], ah[0][0], ah[0][1], ah[0][2], ah[0][3], b0l, b1l);  // hl
                    mma_f16(acc[1][j], ah[1][0], ah[1][1], ah[1][2], ah[1][3], b0h, b1h);
                    mma_f16(acc[1][j], al[1][0], al[1][1], al[1][2], al[1][3], b0h, b1h);
                    mma_f16(acc[1][j], ah[1][0], ah[1][1], ah[1][2], ah[1][3], b0l, b1l);
                }
            }
        }
        __syncthreads();
    }

    // ---- epilogue: write split-K partial tile (undo ESCALE) ----
    float* P = g_partial + (size_t)(z * NSPLIT + s) * kd;
    const int rsub = l >> 2;
    const int csub = (l & 3) * 2;
    #pragma unroll
    for (int mt = 0; mt < 2; mt++) {
        #pragma unroll
        for (int j = 0; j < 8; j++) {
            int row = mbase + mt * 16 + rsub;
            int col = ntile * 128 + warpN * 64 + j * 8 + csub;
            *(float2*)(P + (size_t)row * DDIM + col) =
                make_float2(acc[mt][j][0] * EINV, acc[mt][j][1] * EINV);
            *(float2*)(P + (size_t)(row + 8) * DDIM + col) =
                make_float2(acc[mt][j][2] * EINV, acc[mt][j][3] * EINV);
        }
    }
}

// ---------------------------------------------------------------------------
// Kernel 2: deterministic split-K reduction -> g_A, g_B  ([k, d])
// ---------------------------------------------------------------------------
__global__ void reduce_partials(int kd)
{
    int idx = blockIdx.x * blockDim.x + threadIdx.x;
    if (idx >= 2 * kd) return;
    int z = idx / kd;
    int e = idx - z * kd;
    const float* P = g_partial + (size_t)z * NSPLIT * kd;
    float sum = 0.f;
    #pragma unroll 4
    for (int s = 0; s < NSPLIT; s++) sum += P[(size_t)s * kd + e];
    (z ? g_B : g_A)[e] = sum;
}

// ---------------------------------------------------------------------------
// Kernel 3: Gram matrices. AAt[i,j] = A_i . A_j ;  BAt[i,j] = B_i . A_j
// ---------------------------------------------------------------------------
__global__ __launch_bounds__(KDIM)
void gram_kernel(int k, int d)
{
    __shared__ float row[DDIM];
    const int i = blockIdx.x;
    const int z = blockIdx.y;
    const int j = threadIdx.x;
    const float* src = z ? g_B : g_A;
    for (int t = j; t < d; t += KDIM) row[t] = src[i * d + t];
    __syncthreads();
    const float* aj = g_A + j * d;
    float sum = 0.f;
    #pragma unroll 8
    for (int t = 0; t < d; t++) sum = fmaf(row[t], aj[t], sum);
    (z ? g_BAt : g_AAt)[i * k + j] = sum;
}

// ---------------------------------------------------------------------------
// Kernel 4: one CTA per output row i. Blocked Cholesky (NB=16) + fwd/bwd subs.
// ---------------------------------------------------------------------------
__global__ __launch_bounds__(512, 1)
void solve_kernel(const float* __restrict__ evx, const float* __restrict__ evy,
                  float* __restrict__ out)
{
    __shared__ float P[KDIM * (KDIM + 1) / 2];
    __shared__ float colb[NB][KDIM];
    __shared__ float yv[KDIM];
    __shared__ float invD[KDIM];

    const int i   = blockIdx.x;
    const int tid = threadIdx.x;
    const int t   = tid & 127;
    const int q   = tid >> 7;
    const int trit = t * (t + 1) / 2;

    for (int r0 = 0; r0 < KDIM; r0 += 4) {
        int r = r0 + q;
        if (t <= r) P[r * (r + 1) / 2 + t] = g_AAt[r * KDIM + t];
    }
    if (tid < KDIM) yv[tid] = g_BAt[i * KDIM + tid];
    __syncthreads();

    if (tid < KDIM) {
        float ev = evx[tid] - evy[i];
        P[trit + tid] += LAMBDA * ev * ev;
    }
    __syncthreads();

    for (int b = 0; b < KDIM / NB; b++) {
        const int j0  = b * NB;
        const int rlo = j0 + NB;

        if (tid < 32) {
            int lrow = tid & 15;
            int row = j0 + lrow;
            int trow = row * (row + 1) / 2;
            float dreg[NB];
            float myinv = 0.f;
            #pragma unroll
            for (int c = 0; c < NB; c++)
                dreg[c] = (c <= lrow) ? P[trow + j0 + c] : 0.f;

            #pragma unroll
            for (int c = 0; c < NB; c++) {
                float dc = __shfl_sync(0xffffffffu, dreg[c], c);
                float r  = rsqrtf(dc);
                if (lrow == c)      { dreg[c] = dc * r; myinv = r; }
                else if (lrow > c)  dreg[c] *= r;
                #pragma unroll
                for (int m = c + 1; m < NB; m++) {
                    float Lmc = __shfl_sync(0xffffffffu, dreg[c], m);
                    if (lrow >= m) dreg[m] -= dreg[c] * Lmc;
                }
            }
            if (tid < 16) {
                #pragma unroll
                for (int c = 0; c < NB; c++)
                    if (c <= lrow) P[trow + j0 + c] = dreg[c];
                invD[row] = myinv;
            }
        }
        __syncthreads();

        if (rlo >= KDIM) break;

        {
            int r = rlo + tid;
            if (r < KDIM) {
                int trr = r * (r + 1) / 2;
                float a[NB];
                #pragma unroll
                for (int j = 0; j < NB; j++) a[j] = P[trr + j0 + j];
                #pragma unroll
                for (int j = 0; j < NB; j++) {
                    float v = a[j];
                    int trj = (j0 + j) * (j0 + j + 1) / 2;
                    #pragma unroll
                    for (int c = 0; c < j; c++)
                        v -= a[c] * P[trj + j0 + c];
                    a[j] = v * invD[j0 + j];
                }
                #pragma unroll
                for (int j = 0; j < NB; j++) {
                    P[trr + j0 + j] = a[j];
                    colb[j][r] = a[j];
                }
            }
        }
        __syncthreads();

        if (t >= rlo) {
            float ar[NB];
            #pragma unroll
            for (int j = 0; j < NB; j++) ar[j] = colb[j][t];
            for (int c = rlo + q; c <= t; c += 4) {
                float a2 = P[trit + c];
                #pragma unroll
                for (int j = 0; j < NB; j++) a2 -= ar[j] * colb[j][c];
                P[trit + c] = a2;
            }
        }
        __syncthreads();
    }

    for (int b = 0; b < KDIM / NB; b++) {
        const int j0 = b * NB;
        if (tid < 32) {
            int lrow = tid & 15;
            int row = j0 + lrow;
            int trow = row * (row + 1) / 2;
            float yl = yv[row];
            #pragma unroll
            for (int c = 0; c < NB; c++) {
                int rc = j0 + c;
                float t2 = yl * invD[rc];
                yl = (lrow == c) ? t2 : yl;
                float yc = __shfl_sync(0xffffffffu, yl, c);
                if (lrow > c) yl -= P[trow + rc] * yc;
            }
            if (tid < 16) yv[row] = yl;
        }
        __syncthreads();
        {
            int r = j0 + NB + tid;
            if (r < KDIM) {
                int trr = r * (r + 1) / 2;
                float a2 = yv[r];
                #pragma unroll
                for (int c = 0; c < NB; c++)
                    a2 -= P[trr + j0 + c] * yv[j0 + c];
                yv[r] = a2;
            }
        }
        __syncthreads();
    }

    for (int b = KDIM / NB - 1; b >= 0; b--) {
        const int j0 = b * NB;
        if (tid < 32) {
            int lrow = tid & 15;
            int row = j0 + lrow;
            float xl = yv[row];
            #pragma unroll
            for (int c = NB - 1; c >= 0; c--) {
                int rc = j0 + c;
                int trc = rc * (rc + 1) / 2;
                float t2 = xl * invD[rc];
                xl = (lrow == c) ? t2 : xl;
                float xc = __shfl_sync(0xffffffffu, xl, c);
                if (lrow < c) xl -= P[trc + row] * xc;
            }
            if (tid < 16) yv[row] = xl;
        }
        __syncthreads();
        {
            int r = tid;
            if (r < j0) {
                float a2 = yv[r];
                #pragma unroll
                for (int c = 0; c < NB; c++) {
                    int rc = j0 + c;
                    a2 -= P[rc * (rc + 1) / 2 + r] * yv[rc];
                }
                yv[r] = a2;
            }
        }
        __syncthreads();
    }

    if (tid < KDIM) out[i * KDIM + tid] = yv[tid];
}

// ---------------------------------------------------------------------------
// Launch
// ---------------------------------------------------------------------------
extern "C" void kernel_launch(void* const* d_in, const int* in_sizes, int n_in,
                              void* d_out, int out_size)
{
    const float* feat_x = (const float*)d_in[0];
    const float* feat_y = (const float*)d_in[1];
    const float* evals_x = (const float*)d_in[2];
    const float* evals_y = (const float*)d_in[3];
    const float* Ex = (const float*)d_in[4];
    const float* Ey = (const float*)d_in[5];

    const int  k  = in_sizes[2];                  // 128
    const long N  = (long)in_sizes[4] / k;        // 200000
    const int  d  = (int)((long)in_sizes[0] / N); // 256
    const int  kd = k * d;

    int Kc = (int)((N + NSPLIT - 1) / NSPLIT);
    Kc = ((Kc + KB - 1) / KB) * KB;

    cudaFuncSetAttribute(gemm_mma, cudaFuncAttributeMaxDynamicSharedMemorySize, SMEM_GEMM);

    dim3 ggrid(2, NSPLIT, 2);
    gemm_mma<<<ggrid, 256, SMEM_GEMM>>>(Ex, feat_x, Ey, feat_y, (int)N, d, Kc, kd);

    reduce_partials<<<(2 * kd + 255) / 256, 256>>>(kd);

    gram_kernel<<<dim3(k, 2), KDIM>>>(k, d);

    solve_kernel<<<k, 512>>>(evals_x, evals_y, (float*)d_out);
}